// round 2
// baseline (speedup 1.0000x reference)
#include <cuda_runtime.h>
#include <math.h>

#define BB 4
#define NN 8192
#define KNB 9
#define BNK (BB*NN*KNB)
#define TILE 1024
#define BN_EPS 1e-5f

// scratch (allocation-free): padded feature buffer [bnk][8] and BN accumulators
__device__ float g_feat[BNK * 8];
__device__ float g_acc[28];   // [0:7) sum1, [7:14) sumsq1, [14:21) sum2, [21:28) sumsq2

__global__ void k_zero() {
    int t = threadIdx.x;
    if (t < 28) g_acc[t] = 0.f;
}

// branchless sorted insert (desc by d; within-thread ascending j scan => strict >
// keeps lower index ahead on ties, matching jax.lax.top_k)
__device__ __forceinline__ void ins10(float d, int j, float dst[10], int idx[10]) {
    float cd = d; int ci = j;
#pragma unroll
    for (int k = 0; k < 10; k++) {
        bool p = cd > dst[k];
        float td = p ? cd : dst[k];
        float nd = p ? dst[k] : cd;
        int   ti = p ? ci : idx[k];
        int   ni = p ? idx[k] : ci;
        dst[k] = td; idx[k] = ti;
        cd = nd; ci = ni;
    }
}

// ---------------------------------------------------------------------------
// K1: brute-force top-10 (dist = 2*x.y - |x|^2 - |y|^2, desc) + umbrella
//     geometry + first 7x7 linear, accumulate BN1 stats
// ---------------------------------------------------------------------------
__global__ __launch_bounds__(256) void k_knn(const float* __restrict__ x,
                                             const float* __restrict__ w1) {
    __shared__ float4 tile[TILE];
    __shared__ float s_w1[49];

    const int tid = threadIdx.x;
    const int b = blockIdx.x >> 5;                 // 32 blocks per batch
    const int n = (blockIdx.x & 31) * 256 + tid;
    const float* xb = x + (size_t)b * NN * 3;

    if (tid < 49) s_w1[tid] = w1[tid];

    const float x0 = xb[n*3+0], x1 = xb[n*3+1], x2 = xb[n*3+2];
    const float xsqi = fmaf(x2, x2, fmaf(x1, x1, x0*x0));

    float dst[10]; int idx[10];
#pragma unroll
    for (int k = 0; k < 10; k++) { dst[k] = -3.4e38f; idx[k] = -1; }
    float thr = -3.4e38f;

    for (int base = 0; base < NN; base += TILE) {
        __syncthreads();
        for (int j = tid; j < TILE; j += 256) {
            float a  = xb[(base+j)*3+0];
            float c1 = xb[(base+j)*3+1];
            float c2 = xb[(base+j)*3+2];
            tile[j] = make_float4(a, c1, c2, fmaf(c2, c2, fmaf(c1, c1, a*a)));
        }
        __syncthreads();
        for (int j0 = 0; j0 < TILE; j0 += 8) {
            float4 s[8]; float dv[8];
#pragma unroll
            for (int u = 0; u < 8; u++) s[u] = tile[j0 + u];
#pragma unroll
            for (int u = 0; u < 8; u++) {
                float xx = fmaf(x2, s[u].z, fmaf(x1, s[u].y, x0 * s[u].x));
                dv[u] = fmaf(2.0f, xx, -xsqi) - s[u].w;   // same rounding as ref
            }
            // compare vs snapshot thr (no dep on dst[9] inside the block):
            // below-live-threshold inserts are harmless no-ops in ins10.
#pragma unroll
            for (int u = 0; u < 8; u++) {
                if (dv[u] > thr) ins10(dv[u], base + j0 + u, dst, idx);
            }
            thr = dst[9];
        }
    }

    // --- umbrella geometry on the 9 non-self neighbors (idx[1..9]) ---
    float vx[9], vy[9], vz[9], ph[9];
#pragma unroll
    for (int k = 0; k < 9; k++) {
        int j = idx[k+1];
        float ax = xb[j*3+0] - x0;
        float ay = xb[j*3+1] - x1;
        float az = xb[j*3+2] - x2;
        vx[k] = ax; vy[k] = ay; vz[k] = az;
        ph[k] = atan2f(ay, ax);   // monotone in reference phi -> same argsort order
    }
#pragma unroll
    for (int a = 0; a < 8; a++) {
#pragma unroll
        for (int c = 0; c < 8 - a; c++) {
            if (ph[c] > ph[c+1]) {
                float t;
                t = ph[c]; ph[c] = ph[c+1]; ph[c+1] = t;
                t = vx[c]; vx[c] = vx[c+1]; vx[c+1] = t;
                t = vy[c]; vy[c] = vy[c+1]; vy[c+1] = t;
                t = vz[c]; vz[c] = vz[c+1]; vz[c+1] = t;
            }
        }
    }
    float c0x = vy[0]*vz[1] - vz[0]*vy[1] + 1e-5f;
    const float mask = (c0x > 0.f) ? 1.f : -1.f;

    float lsum[7], lsq[7];
#pragma unroll
    for (int o = 0; o < 7; o++) { lsum[o] = 0.f; lsq[o] = 0.f; }

    const int bnkBase = (b * NN + n) * KNB;
#pragma unroll
    for (int k = 0; k < 9; k++) {
        const int k2 = (k + 1 == 9) ? 0 : k + 1;
        float ax = vx[k],  ay = vy[k],  az = vz[k];
        float bx = vx[k2], by = vy[k2], bz = vz[k2];
        float cx = 0.5f*(ax+bx), cy = 0.5f*(ay+by), cz = 0.5f*(az+bz);
        float ux = ay*bz - az*by + 1e-5f;
        float uy = az*bx - ax*bz + 1e-5f;
        float uz = ax*by - ay*bx + 1e-5f;
        float inv = rsqrtf(ux*ux + uy*uy + uz*uz) * mask;
        ux *= inv; uy *= inv; uz *= inv;
        float pos = (cx*ux + cy*uy + cz*uz) * 0.57735026918962576f;  // /sqrt(3)
        float f[7] = {cx, cy, cz, ux, uy, uz, pos};
        float h[7];
#pragma unroll
        for (int o = 0; o < 7; o++) {
            float hh = 0.f;
#pragma unroll
            for (int c = 0; c < 7; c++) hh = fmaf(f[c], s_w1[o*7+c], hh);
            h[o] = hh;
            lsum[o] += hh;
            lsq[o]   = fmaf(hh, hh, lsq[o]);
        }
        float4* fp = (float4*)&g_feat[(size_t)(bnkBase + k) * 8];
        fp[0] = make_float4(h[0], h[1], h[2], h[3]);
        fp[1] = make_float4(h[4], h[5], h[6], 0.f);
    }

    const int lane = tid & 31;
#pragma unroll
    for (int o = 0; o < 7; o++) {
        float s = lsum[o], q = lsq[o];
        for (int off = 16; off; off >>= 1) {
            s += __shfl_xor_sync(0xffffffffu, s, off);
            q += __shfl_xor_sync(0xffffffffu, q, off);
        }
        if (lane == 0) { atomicAdd(&g_acc[o], s); atomicAdd(&g_acc[7+o], q); }
    }
}

// ---------------------------------------------------------------------------
// K2: BN1 + relu + linear2(+bias2), accumulate BN2 stats (in-place on g_feat)
// ---------------------------------------------------------------------------
__global__ __launch_bounds__(256) void k_mlp2(const float* __restrict__ gamma1,
                                              const float* __restrict__ beta1,
                                              const float* __restrict__ w2,
                                              const float* __restrict__ bias2) {
    __shared__ float s_w2[49], s_b2[7], s_scale[7], s_shift[7];
    const int tid = threadIdx.x;
    if (tid < 49) s_w2[tid] = w2[tid];
    if (tid < 7) {
        s_b2[tid] = bias2[tid];
        float m = g_acc[tid] * (1.f / BNK);
        float v = g_acc[7+tid] * (1.f / BNK) - m*m;
        float sc = gamma1[tid] * rsqrtf(v + BN_EPS);
        s_scale[tid] = sc;
        s_shift[tid] = beta1[tid] - m*sc;
    }
    __syncthreads();

    const int bnk = blockIdx.x * 256 + tid;
    float4* f4 = (float4*)g_feat;
    float4 A = f4[bnk*2], Bv = f4[bnk*2+1];
    float hin[7] = {A.x, A.y, A.z, A.w, Bv.x, Bv.y, Bv.z};
    float r[7];
#pragma unroll
    for (int c = 0; c < 7; c++)
        r[c] = fmaxf(fmaf(hin[c], s_scale[c], s_shift[c]), 0.f);

    float h[7], lsum = 0.f;  // (sums handled per-channel below)
    float lsq[7];
#pragma unroll
    for (int o = 0; o < 7; o++) {
        float hh = s_b2[o];
#pragma unroll
        for (int c = 0; c < 7; c++) hh = fmaf(r[c], s_w2[o*7+c], hh);
        h[o] = hh;
        lsq[o] = hh * hh;
    }
    f4[bnk*2]   = make_float4(h[0], h[1], h[2], h[3]);
    f4[bnk*2+1] = make_float4(h[4], h[5], h[6], 0.f);

    const int lane = tid & 31;
#pragma unroll
    for (int o = 0; o < 7; o++) {
        float s = h[o], q = lsq[o];
        for (int off = 16; off; off >>= 1) {
            s += __shfl_xor_sync(0xffffffffu, s, off);
            q += __shfl_xor_sync(0xffffffffu, q, off);
        }
        if (lane == 0) { atomicAdd(&g_acc[14+o], s); atomicAdd(&g_acc[21+o], q); }
    }
    (void)lsum;
}

// ---------------------------------------------------------------------------
// K3: BN2 + relu + linear3(+bias3) + maxpool over K, concat with x -> out
// ---------------------------------------------------------------------------
__global__ __launch_bounds__(256) void k_mlp3(const float* __restrict__ x,
                                              const float* __restrict__ gamma2,
                                              const float* __restrict__ beta2,
                                              const float* __restrict__ w3,
                                              const float* __restrict__ bias3,
                                              float* __restrict__ out) {
    __shared__ float s_w3[49], s_b3[7], s_scale[7], s_shift[7];
    const int tid = threadIdx.x;
    if (tid < 49) s_w3[tid] = w3[tid];
    if (tid < 7) {
        s_b3[tid] = bias3[tid];
        float m = g_acc[14+tid] * (1.f / BNK);
        float v = g_acc[21+tid] * (1.f / BNK) - m*m;
        float sc = gamma2[tid] * rsqrtf(v + BN_EPS);
        s_scale[tid] = sc;
        s_shift[tid] = beta2[tid] - m*sc;
    }
    __syncthreads();

    const int bn = blockIdx.x * 256 + tid;   // 0 .. B*N-1
    const float4* f4 = (const float4*)g_feat;
    float best[7];
#pragma unroll
    for (int o = 0; o < 7; o++) best[o] = -3.4e38f;

#pragma unroll
    for (int k = 0; k < 9; k++) {
        float4 A = f4[(bn*9 + k)*2], Bv = f4[(bn*9 + k)*2 + 1];
        float hin[7] = {A.x, A.y, A.z, A.w, Bv.x, Bv.y, Bv.z};
        float r[7];
#pragma unroll
        for (int c = 0; c < 7; c++)
            r[c] = fmaxf(fmaf(hin[c], s_scale[c], s_shift[c]), 0.f);
#pragma unroll
        for (int o = 0; o < 7; o++) {
            float hh = s_b3[o];
#pragma unroll
            for (int c = 0; c < 7; c++) hh = fmaf(r[c], s_w3[o*7+c], hh);
            best[o] = fmaxf(best[o], hh);
        }
    }
    out[bn*10+0] = x[bn*3+0];
    out[bn*10+1] = x[bn*3+1];
    out[bn*10+2] = x[bn*3+2];
#pragma unroll
    for (int o = 0; o < 7; o++) out[bn*10+3+o] = best[o];
}

extern "C" void kernel_launch(void* const* d_in, const int* in_sizes, int n_in,
                              void* d_out, int out_size) {
    const float* x      = (const float*)d_in[0];
    const float* w1     = (const float*)d_in[1];
    const float* gamma1 = (const float*)d_in[2];
    const float* beta1  = (const float*)d_in[3];
    const float* w2     = (const float*)d_in[4];
    const float* bias2  = (const float*)d_in[5];
    const float* gamma2 = (const float*)d_in[6];
    const float* beta2  = (const float*)d_in[7];
    const float* w3     = (const float*)d_in[8];
    const float* bias3  = (const float*)d_in[9];
    float* out = (float*)d_out;

    k_zero<<<1, 32>>>();
    k_knn<<<BB * (NN / 256), 256>>>(x, w1);
    k_mlp2<<<BNK / 256, 256>>>(gamma1, beta1, w2, bias2);
    k_mlp3<<<(BB * NN) / 256, 256>>>(x, gamma2, beta2, w3, bias3, out);
}

// round 6
// speedup vs baseline: 1.3581x; 1.3581x over previous
#include <cuda_runtime.h>
#include <math.h>

#define BB 4
#define NN 8192
#define KNB 9
#define CH 7
#define BNK (BB*NN*KNB)
#define TILE 1024
#define BN_EPS 1e-5f
#define NEGINF (-3.4e38f)

// scratch (allocation-free): SoA feature buffer [channel][bnk] and BN accumulators
__device__ float g_feat[CH * BNK];
__device__ float g_acc[28];   // [0:7) sum1, [7:14) sumsq1, [14:21) sum2, [21:28) sumsq2

__global__ void k_zero() {
    int t = threadIdx.x;
    if (t < 28) g_acc[t] = 0.f;
}

// branchless sorted insert (desc by d; ascending-j scan + strict > keeps lower
// index ahead on ties, matching jax.lax.top_k). cd==NEGINF is a guaranteed no-op.
__device__ __forceinline__ void ins10(float cd, int ci, float dst[10], int idx[10]) {
#pragma unroll
    for (int k = 0; k < 10; k++) {
        bool p = cd > dst[k];
        float td = p ? cd : dst[k];
        float nd = p ? dst[k] : cd;
        int   ti = p ? ci : idx[k];
        int   ni = p ? idx[k] : ci;
        dst[k] = td; idx[k] = ti;
        cd = nd; ci = ni;
    }
}

// ---------------------------------------------------------------------------
// K1: brute-force top-10 (dist = 2*x.y - |x|^2 - |y|^2, desc) + umbrella
//     geometry + first 7x7 linear, accumulate BN1 stats
// ---------------------------------------------------------------------------
__global__ __launch_bounds__(256) void k_knn(const float* __restrict__ x,
                                             const float* __restrict__ w1) {
    __shared__ float4 tile[TILE];
    __shared__ float s_w1[49];
    __shared__ float s_acc[14];

    const int tid = threadIdx.x;
    const int b = blockIdx.x >> 5;                 // 32 blocks per batch
    const int n = (blockIdx.x & 31) * 256 + tid;
    const float* xb = x + (size_t)b * NN * 3;

    if (tid < 49) s_w1[tid] = w1[tid];
    if (tid < 14) s_acc[tid] = 0.f;

    const float x0 = xb[n*3+0], x1 = xb[n*3+1], x2 = xb[n*3+2];
    const float xsqi = fmaf(x2, x2, fmaf(x1, x1, x0*x0));

    float dst[10]; int idx[10];
#pragma unroll
    for (int k = 0; k < 10; k++) { dst[k] = NEGINF; idx[k] = -1; }
    float thr = NEGINF;

    for (int base = 0; base < NN; base += TILE) {
        __syncthreads();
        for (int j = tid; j < TILE; j += 256) {
            float a  = xb[(base+j)*3+0];
            float c1 = xb[(base+j)*3+1];
            float c2 = xb[(base+j)*3+2];
            tile[j] = make_float4(a, c1, c2, fmaf(c2, c2, fmaf(c1, c1, a*a)));
        }
        __syncthreads();
#pragma unroll 8
        for (int j = 0; j < TILE; j++) {
            float4 s = tile[j];
            float t = x0 * s.x;
            t = fmaf(x1, s.y, t);
            t = fmaf(x2, s.z, t);
            float d = fmaf(2.0f, t, -xsqi) - s.w;     // same rounding as ref
            bool p = d > thr;
            // warp-uniform branch: no divergence; non-survivor lanes run a no-op
            if (__any_sync(0xffffffffu, p)) {
                ins10(p ? d : NEGINF, base + j, dst, idx);
                thr = dst[9];
            }
        }
    }

    // --- umbrella geometry on the 9 non-self neighbors (idx[1..9]) ---
    float vx[9], vy[9], vz[9], ph[9];
#pragma unroll
    for (int k = 0; k < 9; k++) {
        int j = idx[k+1];
        float ax = xb[j*3+0] - x0;
        float ay = xb[j*3+1] - x1;
        float az = xb[j*3+2] - x2;
        vx[k] = ax; vy[k] = ay; vz[k] = az;
        ph[k] = atan2f(ay, ax);   // monotone in reference phi -> same argsort order
    }
#pragma unroll
    for (int a = 0; a < 8; a++) {
#pragma unroll
        for (int c = 0; c < 8 - a; c++) {
            if (ph[c] > ph[c+1]) {
                float t;
                t = ph[c]; ph[c] = ph[c+1]; ph[c+1] = t;
                t = vx[c]; vx[c] = vx[c+1]; vx[c+1] = t;
                t = vy[c]; vy[c] = vy[c+1]; vy[c+1] = t;
                t = vz[c]; vz[c] = vz[c+1]; vz[c+1] = t;
            }
        }
    }
    float c0x = vy[0]*vz[1] - vz[0]*vy[1] + 1e-5f;
    const float mask = (c0x > 0.f) ? 1.f : -1.f;

    float lsum[7], lsq[7];
#pragma unroll
    for (int o = 0; o < 7; o++) { lsum[o] = 0.f; lsq[o] = 0.f; }

    const int bnkBase = (b * NN + n) * KNB;
#pragma unroll
    for (int k = 0; k < 9; k++) {
        const int k2 = (k + 1 == 9) ? 0 : k + 1;
        float ax = vx[k],  ay = vy[k],  az = vz[k];
        float bx = vx[k2], by = vy[k2], bz = vz[k2];
        float cx = 0.5f*(ax+bx), cy = 0.5f*(ay+by), cz = 0.5f*(az+bz);
        float ux = ay*bz - az*by + 1e-5f;
        float uy = az*bx - ax*bz + 1e-5f;
        float uz = ax*by - ay*bx + 1e-5f;
        float inv = rsqrtf(ux*ux + uy*uy + uz*uz) * mask;
        ux *= inv; uy *= inv; uz *= inv;
        float pos = (cx*ux + cy*uy + cz*uz) * 0.57735026918962576f;  // /sqrt(3)
        float f[7] = {cx, cy, cz, ux, uy, uz, pos};
#pragma unroll
        for (int o = 0; o < 7; o++) {
            float h = 0.f;
#pragma unroll
            for (int c = 0; c < 7; c++) h = fmaf(f[c], s_w1[o*7+c], h);
            g_feat[o*BNK + bnkBase + k] = h;
            lsum[o] += h;
            lsq[o]   = fmaf(h, h, lsq[o]);
        }
    }

    const int lane = tid & 31;
#pragma unroll
    for (int o = 0; o < 7; o++) {
        float s = lsum[o], q = lsq[o];
        for (int off = 16; off; off >>= 1) {
            s += __shfl_xor_sync(0xffffffffu, s, off);
            q += __shfl_xor_sync(0xffffffffu, q, off);
        }
        if (lane == 0) { atomicAdd(&s_acc[o], s); atomicAdd(&s_acc[7+o], q); }
    }
    __syncthreads();
    if (tid < 14) atomicAdd(&g_acc[tid], s_acc[tid]);
}

// ---------------------------------------------------------------------------
// K2: BN1 + relu + linear2(+bias2), accumulate BN2 stats (in-place on g_feat)
// ---------------------------------------------------------------------------
__global__ __launch_bounds__(256) void k_mlp2(const float* __restrict__ gamma1,
                                              const float* __restrict__ beta1,
                                              const float* __restrict__ w2,
                                              const float* __restrict__ bias2) {
    __shared__ float s_w2[49], s_b2[7], s_scale[7], s_shift[7], s_acc[14];
    const int tid = threadIdx.x;
    if (tid < 49) s_w2[tid] = w2[tid];
    if (tid < 7) {
        s_b2[tid] = bias2[tid];
        float m = g_acc[tid] * (1.f / BNK);
        float v = g_acc[7+tid] * (1.f / BNK) - m*m;
        float sc = gamma1[tid] * rsqrtf(v + BN_EPS);
        s_scale[tid] = sc;
        s_shift[tid] = beta1[tid] - m*sc;
    }
    if (tid < 14) s_acc[tid] = 0.f;
    __syncthreads();

    const int bnk = blockIdx.x * 256 + tid;
    float r[7];
#pragma unroll
    for (int c = 0; c < 7; c++) {
        float h = g_feat[c*BNK + bnk];
        h = fmaf(h, s_scale[c], s_shift[c]);
        r[c] = fmaxf(h, 0.f);
    }
    float h[7], lsq[7];
#pragma unroll
    for (int o = 0; o < 7; o++) {
        float hh = s_b2[o];
#pragma unroll
        for (int c = 0; c < 7; c++) hh = fmaf(r[c], s_w2[o*7+c], hh);
        g_feat[o*BNK + bnk] = hh;
        h[o] = hh;
        lsq[o] = hh * hh;
    }
    const int lane = tid & 31;
#pragma unroll
    for (int o = 0; o < 7; o++) {
        float s = h[o], q = lsq[o];
        for (int off = 16; off; off >>= 1) {
            s += __shfl_xor_sync(0xffffffffu, s, off);
            q += __shfl_xor_sync(0xffffffffu, q, off);
        }
        if (lane == 0) { atomicAdd(&s_acc[o], s); atomicAdd(&s_acc[7+o], q); }
    }
    __syncthreads();
    if (tid < 14) atomicAdd(&g_acc[14+tid], s_acc[tid]);
}

// ---------------------------------------------------------------------------
// K3: BN2 + relu + linear3(+bias3) + maxpool over K, concat with x -> out
// ---------------------------------------------------------------------------
__global__ __launch_bounds__(256) void k_mlp3(const float* __restrict__ x,
                                              const float* __restrict__ gamma2,
                                              const float* __restrict__ beta2,
                                              const float* __restrict__ w3,
                                              const float* __restrict__ bias3,
                                              float* __restrict__ out) {
    __shared__ float s_w3[49], s_b3[7], s_scale[7], s_shift[7];
    const int tid = threadIdx.x;
    if (tid < 49) s_w3[tid] = w3[tid];
    if (tid < 7) {
        s_b3[tid] = bias3[tid];
        float m = g_acc[14+tid] * (1.f / BNK);
        float v = g_acc[21+tid] * (1.f / BNK) - m*m;
        float sc = gamma2[tid] * rsqrtf(v + BN_EPS);
        s_scale[tid] = sc;
        s_shift[tid] = beta2[tid] - m*sc;
    }
    __syncthreads();

    const int bn = blockIdx.x * 256 + tid;   // 0 .. B*N-1
    float best[7];
#pragma unroll
    for (int o = 0; o < 7; o++) best[o] = NEGINF;

#pragma unroll
    for (int k = 0; k < 9; k++) {
        float r[7];
#pragma unroll
        for (int c = 0; c < 7; c++) {
            float h = g_feat[c*BNK + bn*KNB + k];
            h = fmaf(h, s_scale[c], s_shift[c]);
            r[c] = fmaxf(h, 0.f);
        }
#pragma unroll
        for (int o = 0; o < 7; o++) {
            float h = s_b3[o];
#pragma unroll
            for (int c = 0; c < 7; c++) h = fmaf(r[c], s_w3[o*7+c], h);
            best[o] = fmaxf(best[o], h);
        }
    }
    out[bn*10+0] = x[bn*3+0];
    out[bn*10+1] = x[bn*3+1];
    out[bn*10+2] = x[bn*3+2];
#pragma unroll
    for (int o = 0; o < 7; o++) out[bn*10+3+o] = best[o];
}

extern "C" void kernel_launch(void* const* d_in, const int* in_sizes, int n_in,
                              void* d_out, int out_size) {
    const float* x      = (const float*)d_in[0];
    const float* w1     = (const float*)d_in[1];
    const float* gamma1 = (const float*)d_in[2];
    const float* beta1  = (const float*)d_in[3];
    const float* w2     = (const float*)d_in[4];
    const float* bias2  = (const float*)d_in[5];
    const float* gamma2 = (const float*)d_in[6];
    const float* beta2  = (const float*)d_in[7];
    const float* w3     = (const float*)d_in[8];
    const float* bias3  = (const float*)d_in[9];
    float* out = (float*)d_out;

    k_zero<<<1, 32>>>();
    k_knn<<<BB * (NN / 256), 256>>>(x, w1);
    k_mlp2<<<BNK / 256, 256>>>(gamma1, beta1, w2, bias2);
    k_mlp3<<<(BB * NN) / 256, 256>>>(x, gamma2, beta2, w3, bias3, out);
}

// round 8
// speedup vs baseline: 1.7264x; 1.2712x over previous
#include <cuda_runtime.h>
#include <math.h>

#define BB 4
#define NN 8192
#define KNB 9
#define CH 7
#define BNK (BB*NN*KNB)
#define TILE 1024
#define BN_EPS 1e-5f
#define NEGINF (-3.4e38f)

// scratch (allocation-free): SoA feature buffer [channel][bnk] and BN accumulators
__device__ float g_feat[CH * BNK];
__device__ float g_acc[28];   // [0:7) sum1, [7:14) sumsq1, [14:21) sum2, [21:28) sumsq2

__global__ void k_zero() {
    int t = threadIdx.x;
    if (t < 28) g_acc[t] = 0.f;
}

// Parallel-select sorted insert (desc). One value inserts at pos = #{dst[k] >= d}:
// all predicates independent, all outputs read only pre-insert state -> depth 2
// instead of a 10-level dependent chain. Strict > keeps lower index on ties
// (ascending-j scan), matching jax.lax.top_k. d==NEGINF is a guaranteed no-op.
__device__ __forceinline__ void ins10(float d, int j, float dst[10], int idx[10]) {
    bool p[10];
#pragma unroll
    for (int k = 0; k < 10; k++) p[k] = d > dst[k];
#pragma unroll
    for (int k = 9; k >= 1; k--) {
        dst[k] = p[k] ? (p[k-1] ? dst[k-1] : d) : dst[k];
        idx[k] = p[k] ? (p[k-1] ? idx[k-1] : j) : idx[k];
    }
    dst[0] = p[0] ? d : dst[0];
    idx[0] = p[0] ? j : idx[0];
}

// ---------------------------------------------------------------------------
// K1: brute-force top-10 (dist = 2*x.y - |x|^2 - |y|^2, desc) + umbrella
//     geometry + first 7x7 linear, accumulate BN1 stats
// ---------------------------------------------------------------------------
__global__ __launch_bounds__(256) void k_knn(const float* __restrict__ x,
                                             const float* __restrict__ w1) {
    __shared__ float4 tile[TILE];
    __shared__ float s_w1[49];
    __shared__ float s_acc[14];

    const int tid = threadIdx.x;
    const int b = blockIdx.x >> 5;                 // 32 blocks per batch
    const int n = (blockIdx.x & 31) * 256 + tid;
    const float* xb = x + (size_t)b * NN * 3;

    if (tid < 49) s_w1[tid] = w1[tid];
    if (tid < 14) s_acc[tid] = 0.f;

    const float x0 = xb[n*3+0], x1 = xb[n*3+1], x2 = xb[n*3+2];
    const float xsqi = fmaf(x2, x2, fmaf(x1, x1, x0*x0));

    float dst[10]; int idx[10];
#pragma unroll
    for (int k = 0; k < 10; k++) { dst[k] = NEGINF; idx[k] = -1; }
    float thr = NEGINF;

    for (int base = 0; base < NN; base += TILE) {
        __syncthreads();
        for (int j = tid; j < TILE; j += 256) {
            float a  = xb[(base+j)*3+0];
            float c1 = xb[(base+j)*3+1];
            float c2 = xb[(base+j)*3+2];
            tile[j] = make_float4(a, c1, c2, fmaf(c2, c2, fmaf(c1, c1, a*a)));
        }
        __syncthreads();
        for (int j0 = 0; j0 < TILE; j0 += 8) {
            float dv[8];
#pragma unroll
            for (int u = 0; u < 8; u++) {
                float4 s = tile[j0 + u];           // uniform addr -> smem broadcast
                float t = x0 * s.x;
                t = fmaf(x1, s.y, t);
                t = fmaf(x2, s.z, t);
                dv[u] = fmaf(2.0f, t, -xsqi) - s.w; // same rounding as ref
            }
            // 8-wide pre-screen: one vote/branch per 8 candidates
            float m01 = fmaxf(dv[0], dv[1]), m23 = fmaxf(dv[2], dv[3]);
            float m45 = fmaxf(dv[4], dv[5]), m67 = fmaxf(dv[6], dv[7]);
            float m = fmaxf(fmaxf(m01, m23), fmaxf(m45, m67));
            if (__any_sync(0xffffffffu, m > thr)) {
#pragma unroll
                for (int u = 0; u < 8; u++) {
                    bool p = dv[u] > thr;
                    // warp-uniform: non-survivor lanes run a guaranteed no-op
                    if (__any_sync(0xffffffffu, p)) {
                        ins10(p ? dv[u] : NEGINF, base + j0 + u, dst, idx);
                        thr = dst[9];
                    }
                }
            }
        }
    }

    // --- umbrella geometry on the 9 non-self neighbors (idx[1..9]) ---
    float vx[9], vy[9], vz[9], ph[9];
#pragma unroll
    for (int k = 0; k < 9; k++) {
        int j = idx[k+1];
        float ax = xb[j*3+0] - x0;
        float ay = xb[j*3+1] - x1;
        float az = xb[j*3+2] - x2;
        vx[k] = ax; vy[k] = ay; vz[k] = az;
        ph[k] = atan2f(ay, ax);   // monotone in reference phi -> same argsort order
    }
#pragma unroll
    for (int a = 0; a < 8; a++) {
#pragma unroll
        for (int c = 0; c < 8 - a; c++) {
            if (ph[c] > ph[c+1]) {
                float t;
                t = ph[c]; ph[c] = ph[c+1]; ph[c+1] = t;
                t = vx[c]; vx[c] = vx[c+1]; vx[c+1] = t;
                t = vy[c]; vy[c] = vy[c+1]; vy[c+1] = t;
                t = vz[c]; vz[c] = vz[c+1]; vz[c+1] = t;
            }
        }
    }
    float c0x = vy[0]*vz[1] - vz[0]*vy[1] + 1e-5f;
    const float mask = (c0x > 0.f) ? 1.f : -1.f;

    float lsum[7], lsq[7];
#pragma unroll
    for (int o = 0; o < 7; o++) { lsum[o] = 0.f; lsq[o] = 0.f; }

    const int bnkBase = (b * NN + n) * KNB;
#pragma unroll
    for (int k = 0; k < 9; k++) {
        const int k2 = (k + 1 == 9) ? 0 : k + 1;
        float ax = vx[k],  ay = vy[k],  az = vz[k];
        float bx = vx[k2], by = vy[k2], bz = vz[k2];
        float cx = 0.5f*(ax+bx), cy = 0.5f*(ay+by), cz = 0.5f*(az+bz);
        float ux = ay*bz - az*by + 1e-5f;
        float uy = az*bx - ax*bz + 1e-5f;
        float uz = ax*by - ay*bx + 1e-5f;
        float inv = rsqrtf(ux*ux + uy*uy + uz*uz) * mask;
        ux *= inv; uy *= inv; uz *= inv;
        float pos = (cx*ux + cy*uy + cz*uz) * 0.57735026918962576f;  // /sqrt(3)
        float f[7] = {cx, cy, cz, ux, uy, uz, pos};
#pragma unroll
        for (int o = 0; o < 7; o++) {
            float h = 0.f;
#pragma unroll
            for (int c = 0; c < 7; c++) h = fmaf(f[c], s_w1[o*7+c], h);
            g_feat[o*BNK + bnkBase + k] = h;
            lsum[o] += h;
            lsq[o]   = fmaf(h, h, lsq[o]);
        }
    }

    const int lane = tid & 31;
#pragma unroll
    for (int o = 0; o < 7; o++) {
        float s = lsum[o], q = lsq[o];
        for (int off = 16; off; off >>= 1) {
            s += __shfl_xor_sync(0xffffffffu, s, off);
            q += __shfl_xor_sync(0xffffffffu, q, off);
        }
        if (lane == 0) { atomicAdd(&s_acc[o], s); atomicAdd(&s_acc[7+o], q); }
    }
    __syncthreads();
    if (tid < 14) atomicAdd(&g_acc[tid], s_acc[tid]);
}

// ---------------------------------------------------------------------------
// K2: BN1 + relu + linear2(+bias2), accumulate BN2 stats (in-place on g_feat)
// ---------------------------------------------------------------------------
__global__ __launch_bounds__(256) void k_mlp2(const float* __restrict__ gamma1,
                                              const float* __restrict__ beta1,
                                              const float* __restrict__ w2,
                                              const float* __restrict__ bias2) {
    __shared__ float s_w2[49], s_b2[7], s_scale[7], s_shift[7], s_acc[14];
    const int tid = threadIdx.x;
    if (tid < 49) s_w2[tid] = w2[tid];
    if (tid < 7) {
        s_b2[tid] = bias2[tid];
        float m = g_acc[tid] * (1.f / BNK);
        float v = g_acc[7+tid] * (1.f / BNK) - m*m;
        float sc = gamma1[tid] * rsqrtf(v + BN_EPS);
        s_scale[tid] = sc;
        s_shift[tid] = beta1[tid] - m*sc;
    }
    if (tid < 14) s_acc[tid] = 0.f;
    __syncthreads();

    const int bnk = blockIdx.x * 256 + tid;
    float r[7];
#pragma unroll
    for (int c = 0; c < 7; c++) {
        float h = g_feat[c*BNK + bnk];
        h = fmaf(h, s_scale[c], s_shift[c]);
        r[c] = fmaxf(h, 0.f);
    }
    float h[7], lsq[7];
#pragma unroll
    for (int o = 0; o < 7; o++) {
        float hh = s_b2[o];
#pragma unroll
        for (int c = 0; c < 7; c++) hh = fmaf(r[c], s_w2[o*7+c], hh);
        g_feat[o*BNK + bnk] = hh;
        h[o] = hh;
        lsq[o] = hh * hh;
    }
    const int lane = tid & 31;
#pragma unroll
    for (int o = 0; o < 7; o++) {
        float s = h[o], q = lsq[o];
        for (int off = 16; off; off >>= 1) {
            s += __shfl_xor_sync(0xffffffffu, s, off);
            q += __shfl_xor_sync(0xffffffffu, q, off);
        }
        if (lane == 0) { atomicAdd(&s_acc[o], s); atomicAdd(&s_acc[7+o], q); }
    }
    __syncthreads();
    if (tid < 14) atomicAdd(&g_acc[14+tid], s_acc[tid]);
}

// ---------------------------------------------------------------------------
// K3: BN2 + relu + linear3(+bias3) + maxpool over K, concat with x -> out
// ---------------------------------------------------------------------------
__global__ __launch_bounds__(256) void k_mlp3(const float* __restrict__ x,
                                              const float* __restrict__ gamma2,
                                              const float* __restrict__ beta2,
                                              const float* __restrict__ w3,
                                              const float* __restrict__ bias3,
                                              float* __restrict__ out) {
    __shared__ float s_w3[49], s_b3[7], s_scale[7], s_shift[7];
    const int tid = threadIdx.x;
    if (tid < 49) s_w3[tid] = w3[tid];
    if (tid < 7) {
        s_b3[tid] = bias3[tid];
        float m = g_acc[14+tid] * (1.f / BNK);
        float v = g_acc[21+tid] * (1.f / BNK) - m*m;
        float sc = gamma2[tid] * rsqrtf(v + BN_EPS);
        s_scale[tid] = sc;
        s_shift[tid] = beta2[tid] - m*sc;
    }
    __syncthreads();

    const int bn = blockIdx.x * 256 + tid;   // 0 .. B*N-1
    float best[7];
#pragma unroll
    for (int o = 0; o < 7; o++) best[o] = NEGINF;

#pragma unroll
    for (int k = 0; k < 9; k++) {
        float r[7];
#pragma unroll
        for (int c = 0; c < 7; c++) {
            float h = g_feat[c*BNK + bn*KNB + k];
            h = fmaf(h, s_scale[c], s_shift[c]);
            r[c] = fmaxf(h, 0.f);
        }
#pragma unroll
        for (int o = 0; o < 7; o++) {
            float h = s_b3[o];
#pragma unroll
            for (int c = 0; c < 7; c++) h = fmaf(r[c], s_w3[o*7+c], h);
            best[o] = fmaxf(best[o], h);
        }
    }
    out[bn*10+0] = x[bn*3+0];
    out[bn*10+1] = x[bn*3+1];
    out[bn*10+2] = x[bn*3+2];
#pragma unroll
    for (int o = 0; o < 7; o++) out[bn*10+3+o] = best[o];
}

extern "C" void kernel_launch(void* const* d_in, const int* in_sizes, int n_in,
                              void* d_out, int out_size) {
    const float* x      = (const float*)d_in[0];
    const float* w1     = (const float*)d_in[1];
    const float* gamma1 = (const float*)d_in[2];
    const float* beta1  = (const float*)d_in[3];
    const float* w2     = (const float*)d_in[4];
    const float* bias2  = (const float*)d_in[5];
    const float* gamma2 = (const float*)d_in[6];
    const float* beta2  = (const float*)d_in[7];
    const float* w3     = (const float*)d_in[8];
    const float* bias3  = (const float*)d_in[9];
    float* out = (float*)d_out;

    k_zero<<<1, 32>>>();
    k_knn<<<BB * (NN / 256), 256>>>(x, w1);
    k_mlp2<<<BNK / 256, 256>>>(gamma1, beta1, w2, bias2);
    k_mlp3<<<(BB * NN) / 256, 256>>>(x, gamma2, beta2, w3, bias3, out);
}